// round 10
// baseline (speedup 1.0000x reference)
#include <cuda_runtime.h>
#include <cuda_bf16.h>
#include <cstdint>

#define BB 2048
#define TRIP 189

// ---------------- scratch (device globals: allocation-guard safe) ----------------
__device__ float g_h1[BB * 64];
__device__ float g_h2[BB * 256];
__device__ float g_h3[BB * 1024];
__device__ float g_h4[BB * 4096];
__device__ float g_t1[BB * 128 * 64];
__device__ float g_t2[BB * 256 * 64];
__device__ float g_sc[4096];
__device__ float g_sh[4096];
__device__ float g_mean[BB];
__device__ float g_rstd[BB];
__device__ float g_sA[129024];
__device__ float g_sB[4096];
// int8 2-digit operand buffers (reused across layers); generous sizes
__device__ int8_t g_A1[129024 * 1024];
__device__ int8_t g_A2[129024 * 1024];
__device__ int8_t g_B1[4096 * 1024];
__device__ int8_t g_B2[4096 * 1024];

// ======================= base-ISA tensor helpers (sm_80+) =======================
__device__ __forceinline__ uint32_t smem_u32(const void* p) {
    uint32_t a;
    asm("{ .reg .u64 t; cvta.to.shared.u64 t, %1; cvt.u32.u64 %0, t; }"
        : "=r"(a) : "l"(p));
    return a;
}
#define LDSM4(r0, r1, r2, r3, addr)                                             \
    asm volatile("ldmatrix.sync.aligned.m8n8.x4.shared.b16 {%0,%1,%2,%3}, [%4];"\
                 : "=r"(r0), "=r"(r1), "=r"(r2), "=r"(r3) : "r"(addr))
#define MMAI8(d, a, b)                                                          \
    asm volatile("mma.sync.aligned.m16n8k32.row.col.s32.s8.s8.s32 "             \
                 "{%0,%1,%2,%3}, {%4,%5,%6,%7}, {%8,%9}, {%0,%1,%2,%3};"        \
                 : "+r"((d)[0]), "+r"((d)[1]), "+r"((d)[2]), "+r"((d)[3])       \
                 : "r"((a)[0]), "r"((a)[1]), "r"((a)[2]), "r"((a)[3]),          \
                   "r"((b)[0]), "r"((b)[1]))
#define CP_ASYNC16(dst, src)                                                    \
    asm volatile("cp.async.cg.shared.global [%0], [%1], 16;" :: "r"(dst), "l"(src))
#define CP_COMMIT() asm volatile("cp.async.commit_group;" ::: "memory")
#define CP_WAIT1() asm volatile("cp.async.wait_group 1;" ::: "memory")
#define CP_WAIT0() asm volatile("cp.async.wait_group 0;" ::: "memory")

__device__ __forceinline__ int swz(int off) { return off ^ ((off >> 3) & 0x70); }

// ======================= int8 GEMM: C = A(M,K) @ B(N,K)^T =======================
// 2-digit int8: x = sA*(x1 + x2/254). 3 passes per K-chunk of 128 int8:
// acc1 += A1*B1; acc2 += A1*B2; acc2 += A2*B1. C = sA*sB*(acc1 + acc2/254).
// Tile 128x128, 8 warps (4Mx2N), double-buffered 4x16KB tiles.
// EPI 0: out row-major (M,Ntot), += bias[col]
// EPI 1: conv: row r=(b*63+m); out[b][o][m+1] = v + bias[o]; out[b][o][0] = 0
#define GSM_TOTAL 131072

__device__ __forceinline__ void cp_tile_i8(const int8_t* __restrict__ src,
                                           int row0, int Kp, int kc,
                                           uint32_t sdst, int tid) {
#pragma unroll
    for (int i = 0; i < 4; i++) {
        int lin = tid + i * 256;
        int r = lin >> 3, c16 = (lin & 7) * 16;
        const char* g = (const char*)(src + (size_t)(row0 + r) * Kp + kc * 128 + c16);
        CP_ASYNC16(sdst + swz(r * 128 + c16), g);
    }
}

template <int EPI>
__global__ __launch_bounds__(256) void imma_gemm(
    const int8_t* __restrict__ A1, const int8_t* __restrict__ A2,
    const int8_t* __restrict__ B1, const int8_t* __restrict__ B2,
    const float* __restrict__ sA, const float* __restrict__ sB,
    const float* __restrict__ bias, float* __restrict__ out, int Kp, int Ntot) {
    extern __shared__ __align__(1024) char smem[];
    uint32_t sb = smem_u32(smem);
    int tid = threadIdx.x, wid = tid >> 5, lane = tid & 31;
    int bn = blockIdx.x * 128, bm = blockIdx.y * 128;  // N fastest -> A L2 reuse
    int mw = wid >> 1, nw = wid & 1;
    int m_base = mw * 32, n_base = nw * 64;

    const int KCP = Kp >> 7;  // chunks of 128 int8

    int acc1[2][8][4], acc2[2][8][4];
#pragma unroll
    for (int mt = 0; mt < 2; mt++)
#pragma unroll
        for (int nt = 0; nt < 8; nt++)
#pragma unroll
            for (int q = 0; q < 4; q++) { acc1[mt][nt][q] = 0; acc2[mt][nt][q] = 0; }

    int a_row = (lane & 15);
    int a_colsel = (lane & 16) ? 16 : 0;
    int b_row = (lane & 7) + ((lane & 16) ? 8 : 0);
    int b_colsel = (lane & 8) ? 16 : 0;

    // prologue
    {
        uint32_t base = sb;
        cp_tile_i8(A1, bm, Kp, 0, base + 0, tid);
        cp_tile_i8(A2, bm, Kp, 0, base + 16384, tid);
        cp_tile_i8(B1, bn, Kp, 0, base + 32768, tid);
        cp_tile_i8(B2, bn, Kp, 0, base + 49152, tid);
        CP_COMMIT();
        if (KCP > 1) {
            base = sb + 65536;
            cp_tile_i8(A1, bm, Kp, 1, base + 0, tid);
            cp_tile_i8(A2, bm, Kp, 1, base + 16384, tid);
            cp_tile_i8(B1, bn, Kp, 1, base + 32768, tid);
            cp_tile_i8(B2, bn, Kp, 1, base + 49152, tid);
            CP_COMMIT();
        }
    }

    for (int kc = 0; kc < KCP; kc++) {
        int buf = kc & 1;
        if (kc < KCP - 1) CP_WAIT1();
        else CP_WAIT0();
        __syncthreads();

        uint32_t base = sb + buf * 65536;
#pragma unroll
        for (int kk = 0; kk < 4; kk++) {
            uint32_t af[2][4];   // A digit-1 frags (later overwritten by digit-2)
            uint32_t b1f[8][2];  // B digit-1 (lives across passes 0 and 2)
            uint32_t b2f[8][2];
            // load A1 + B1, pass 0: acc1 += A1*B1
#pragma unroll
            for (int mt = 0; mt < 2; mt++) {
                int off = (m_base + mt * 16 + a_row) * 128 + kk * 32 + a_colsel;
                LDSM4(af[mt][0], af[mt][1], af[mt][2], af[mt][3],
                      base + 0 + swz(off));
            }
#pragma unroll
            for (int np = 0; np < 4; np++) {
                int off = (n_base + np * 16 + b_row) * 128 + kk * 32 + b_colsel;
                LDSM4(b1f[2 * np][0], b1f[2 * np][1], b1f[2 * np + 1][0],
                      b1f[2 * np + 1][1], base + 32768 + swz(off));
            }
#pragma unroll
            for (int mt = 0; mt < 2; mt++)
#pragma unroll
                for (int nt = 0; nt < 8; nt++) MMAI8(acc1[mt][nt], af[mt], b1f[nt]);
            // load B2, pass 1: acc2 += A1*B2 (reuse af)
#pragma unroll
            for (int np = 0; np < 4; np++) {
                int off = (n_base + np * 16 + b_row) * 128 + kk * 32 + b_colsel;
                LDSM4(b2f[2 * np][0], b2f[2 * np][1], b2f[2 * np + 1][0],
                      b2f[2 * np + 1][1], base + 49152 + swz(off));
            }
#pragma unroll
            for (int mt = 0; mt < 2; mt++)
#pragma unroll
                for (int nt = 0; nt < 8; nt++) MMAI8(acc2[mt][nt], af[mt], b2f[nt]);
            // load A2 into af, pass 2: acc2 += A2*B1 (reuse b1f)
#pragma unroll
            for (int mt = 0; mt < 2; mt++) {
                int off = (m_base + mt * 16 + a_row) * 128 + kk * 32 + a_colsel;
                LDSM4(af[mt][0], af[mt][1], af[mt][2], af[mt][3],
                      base + 16384 + swz(off));
            }
#pragma unroll
            for (int mt = 0; mt < 2; mt++)
#pragma unroll
                for (int nt = 0; nt < 8; nt++) MMAI8(acc2[mt][nt], af[mt], b1f[nt]);
        }
        __syncthreads();
        if (kc + 2 < KCP) {
            int cn = kc + 2;
            uint32_t pb = sb + buf * 65536;
            cp_tile_i8(A1, bm, Kp, cn, pb + 0, tid);
            cp_tile_i8(A2, bm, Kp, cn, pb + 16384, tid);
            cp_tile_i8(B1, bn, Kp, cn, pb + 32768, tid);
            cp_tile_i8(B2, bn, Kp, cn, pb + 49152, tid);
            CP_COMMIT();
        }
    }

    const float IS = 1.0f / 254.0f;
    // ---------------- epilogue ----------------
    if (EPI == 0) {
#pragma unroll
        for (int mt = 0; mt < 2; mt++) {
            int r0 = bm + m_base + mt * 16 + (lane >> 2);
            float sa0 = __ldg(&sA[r0]), sa1 = __ldg(&sA[r0 + 8]);
#pragma unroll
            for (int nt = 0; nt < 8; nt++) {
                int cidx = bn + n_base + nt * 8 + (lane & 3) * 2;
                float sb0 = __ldg(&sB[cidx]), sb1 = __ldg(&sB[cidx + 1]);
                float bx = __ldg(&bias[cidx]), by = __ldg(&bias[cidx + 1]);
                float c0 = (float)acc1[mt][nt][0] + (float)acc2[mt][nt][0] * IS;
                float c1 = (float)acc1[mt][nt][1] + (float)acc2[mt][nt][1] * IS;
                float c2 = (float)acc1[mt][nt][2] + (float)acc2[mt][nt][2] * IS;
                float c3 = (float)acc1[mt][nt][3] + (float)acc2[mt][nt][3] * IS;
                float2 v0 = {c0 * sa0 * sb0 + bx, c1 * sa0 * sb1 + by};
                float2 v1 = {c2 * sa1 * sb0 + bx, c3 * sa1 * sb1 + by};
                *(float2*)(out + (size_t)r0 * Ntot + cidx) = v0;
                *(float2*)(out + (size_t)(r0 + 8) * Ntot + cidx) = v1;
            }
        }
    } else {
        const int PAD = 129;
        float* S = (float*)smem;
        __syncthreads();
#pragma unroll
        for (int mt = 0; mt < 2; mt++) {
            int r0l = m_base + mt * 16 + (lane >> 2);
            float sa0 = __ldg(&sA[bm + r0l]), sa1 = __ldg(&sA[bm + r0l + 8]);
#pragma unroll
            for (int nt = 0; nt < 8; nt++) {
                int cidx = n_base + nt * 8 + (lane & 3) * 2;
                float sb0 = __ldg(&sB[bn + cidx]), sb1 = __ldg(&sB[bn + cidx + 1]);
                float c0 = (float)acc1[mt][nt][0] + (float)acc2[mt][nt][0] * IS;
                float c1 = (float)acc1[mt][nt][1] + (float)acc2[mt][nt][1] * IS;
                float c2 = (float)acc1[mt][nt][2] + (float)acc2[mt][nt][2] * IS;
                float c3 = (float)acc1[mt][nt][3] + (float)acc2[mt][nt][3] * IS;
                S[r0l * PAD + cidx] = c0 * sa0 * sb0;
                S[r0l * PAD + cidx + 1] = c1 * sa0 * sb1;
                S[(r0l + 8) * PAD + cidx] = c2 * sa1 * sb0;
                S[(r0l + 8) * PAD + cidx + 1] = c3 * sa1 * sb1;
            }
        }
        __syncthreads();
        for (int e = tid; e < 128 * 128; e += 256) {
            int o = e >> 7;
            int lr = e & 127;
            int r = bm + lr;
            int b = r / 63;
            int m = r - b * 63;
            int oo = bn + o;
            float v = S[lr * PAD + o] + __ldg(&bias[oo]);
            float* ob = out + (size_t)b * Ntot * 64 + (size_t)oo * 64;
            ob[m + 1] = v;
            if (m == 0) ob[0] = 0.f;
        }
    }
}

// ======================= quantization prep kernels =======================
__device__ __forceinline__ void quant2(float v, float inv, char& d1, char& d2) {
    float q = v * inv;
    float x1 = rintf(q);
    float x2 = rintf((q - x1) * 254.f);
    d1 = (char)(int)x1;
    d2 = (char)(int)x2;
}

// act (BN affine + lrelu) -> per-row max -> 2-digit int8. One block (128) per row.
__global__ __launch_bounds__(128) void actsplit_i8(
    const float* __restrict__ in, const float* __restrict__ sc,
    const float* __restrict__ sh, int8_t* __restrict__ A1,
    int8_t* __restrict__ A2, float* __restrict__ sA, int K, int Kp) {
    __shared__ float xs[1024];
    __shared__ float red[128];
    int row = blockIdx.x, tid = threadIdx.x;
    const float* ir = in + (size_t)row * K;
    float mx = 0.f;
    for (int i = tid; i < K; i += 128) {
        float v = fmaf(sc[i], ir[i], sh[i]);
        v = v > 0.f ? v : 0.01f * v;
        xs[i] = v;
        mx = fmaxf(mx, fabsf(v));
    }
    red[tid] = mx;
    __syncthreads();
    for (int st = 64; st > 0; st >>= 1) {
        if (tid < st) red[tid] = fmaxf(red[tid], red[tid + st]);
        __syncthreads();
    }
    float s = red[0] > 0.f ? red[0] * (1.f / 127.f) : 1.f;
    float inv = 1.f / s;
    if (tid == 0) sA[row] = s;
    char4* p1 = (char4*)(A1 + (size_t)row * Kp);
    char4* p2 = (char4*)(A2 + (size_t)row * Kp);
    for (int g = tid; g < (Kp >> 2); g += 128) {
        char4 o1, o2;
        char* a1 = (char*)&o1;
        char* a2 = (char*)&o2;
#pragma unroll
        for (int j = 0; j < 4; j++) {
            int k = 4 * g + j;
            if (k < K) quant2(xs[k], inv, a1[j], a2[j]);
            else { a1[j] = 0; a2[j] = 0; }
        }
        p1[g] = o1;
        p2[g] = o2;
    }
}

// weight rows -> per-row max -> 2-digit int8. One block (128) per row.
__global__ __launch_bounds__(128) void wsplit_i8(
    const float* __restrict__ w, int8_t* __restrict__ B1,
    int8_t* __restrict__ B2, float* __restrict__ sB, int K, int Kp) {
    __shared__ float xs[1024];
    __shared__ float red[128];
    int row = blockIdx.x, tid = threadIdx.x;
    const float* ir = w + (size_t)row * K;
    float mx = 0.f;
    for (int i = tid; i < K; i += 128) {
        float v = ir[i];
        xs[i] = v;
        mx = fmaxf(mx, fabsf(v));
    }
    red[tid] = mx;
    __syncthreads();
    for (int st = 64; st > 0; st >>= 1) {
        if (tid < st) red[tid] = fmaxf(red[tid], red[tid + st]);
        __syncthreads();
    }
    float s = red[0] > 0.f ? red[0] * (1.f / 127.f) : 1.f;
    float inv = 1.f / s;
    if (tid == 0) sB[row] = s;
    char4* p1 = (char4*)(B1 + (size_t)row * Kp);
    char4* p2 = (char4*)(B2 + (size_t)row * Kp);
    for (int g = tid; g < (Kp >> 2); g += 128) {
        char4 o1, o2;
        char* a1 = (char*)&o1;
        char* a2 = (char*)&o2;
#pragma unroll
        for (int j = 0; j < 4; j++) {
            int k = 4 * g + j;
            if (k < K) quant2(xs[k], inv, a1[j], a2[j]);
            else { a1[j] = 0; a2[j] = 0; }
        }
        p1[g] = o1;
        p2[g] = o2;
    }
}

// gather + normalize + lrelu + per-row quantize -> E(b*63+m, Kp) int8 x2 digits
// MODE 0: per-feature affine sc/sh; MODE 1: per-sample mean/rstd
template <int CIN, int MODE>
__global__ __launch_bounds__(256) void gather_i8(
    const float* __restrict__ in, const int* __restrict__ idx,
    const float* __restrict__ sc, const float* __restrict__ sh,
    const float* __restrict__ smean, const float* __restrict__ srstd,
    int8_t* __restrict__ E1, int8_t* __restrict__ E2,
    float* __restrict__ sA, int Kp) {
    extern __shared__ float xs[];
    __shared__ int sidx[TRIP];
    __shared__ float sinv[63];
    const int K = 3 * CIN;
    int b = blockIdx.x, tid = threadIdx.x;
    int wid = tid >> 5, lane = tid & 31;
    for (int j = tid; j < TRIP; j += 256) sidx[j] = idx[b * TRIP + j];
    float m_ = 0.f, r_ = 0.f;
    if (MODE == 1) {
        m_ = smean[b];
        r_ = srstd[b];
    }
    const float* xb = in + (size_t)b * CIN * 64;
    for (int i = tid; i < CIN * 64; i += 256) {
        float v = xb[i];
        if (MODE == 0)
            v = fmaf(__ldg(&sc[i]), v, __ldg(&sh[i]));
        else
            v = (v - m_) * r_;
        v = v > 0.f ? v : 0.01f * v;
        xs[i] = v;
    }
    __syncthreads();
    // per-row (m) absmax: warp per row
    for (int m = wid; m < 63; m += 8) {
        float mx = 0.f;
        for (int t = lane; t < K; t += 32) {
            int c = t / 3, k = t - 3 * c;
            float v = xs[c * 64 + sidx[3 * m + k]];
            mx = fmaxf(mx, fabsf(v));
        }
#pragma unroll
        for (int off = 16; off > 0; off >>= 1)
            mx = fmaxf(mx, __shfl_xor_sync(0xffffffff, mx, off));
        if (lane == 0) {
            float s = mx > 0.f ? mx * (1.f / 127.f) : 1.f;
            sinv[m] = 1.f / s;
            sA[(size_t)b * 63 + m] = s;
        }
    }
    __syncthreads();
    const int G = Kp >> 2;
    for (int f = tid; f < 63 * G; f += 256) {
        int m = f / G;
        int g = f - m * G;
        float inv = sinv[m];
        char4 o1, o2;
        char* a1 = (char*)&o1;
        char* a2 = (char*)&o2;
#pragma unroll
        for (int j = 0; j < 4; j++) {
            int t = 4 * g + j;
            if (t < K) {
                int c = t / 3, k = t - 3 * c;
                float v = xs[c * 64 + sidx[3 * m + k]];
                quant2(v, inv, a1[j], a2[j]);
            } else { a1[j] = 0; a2[j] = 0; }
        }
        size_t ro = (size_t)(b * 63 + m) * Kp;
        ((char4*)(E1 + ro))[g] = o1;
        ((char4*)(E2 + ro))[g] = o2;
    }
}

// ======================= fp32 MLP layer-1 GEMM (tiny) =======================
__global__ __launch_bounds__(256) void mlp_gemm0(
    const float* __restrict__ A, const float* __restrict__ W,
    const float* __restrict__ bias, float* __restrict__ P, int K, int N) {
    __shared__ float As[16][64];
    __shared__ float Bs[16][64];
    int tid = threadIdx.x;
    int bm = blockIdx.x * 64, bn = blockIdx.y * 64;
    int lr = tid >> 2, lk = (tid & 3) * 4;
    int tx = tid & 15, ty = tid >> 4;
    float acc[4][4];
#pragma unroll
    for (int r = 0; r < 4; r++)
#pragma unroll
        for (int c = 0; c < 4; c++) acc[r][c] = 0.f;
    for (int k0 = 0; k0 < K; k0 += 16) {
        float4 a = *(const float4*)(A + (size_t)(bm + lr) * K + k0 + lk);
        float4 w4 = *(const float4*)(W + (size_t)(bn + lr) * K + k0 + lk);
        As[lk + 0][lr] = a.x; As[lk + 1][lr] = a.y;
        As[lk + 2][lr] = a.z; As[lk + 3][lr] = a.w;
        Bs[lk + 0][lr] = w4.x; Bs[lk + 1][lr] = w4.y;
        Bs[lk + 2][lr] = w4.z; Bs[lk + 3][lr] = w4.w;
        __syncthreads();
#pragma unroll
        for (int kk = 0; kk < 16; kk++) {
            float4 av = *(const float4*)&As[kk][ty * 4];
            float4 bv = *(const float4*)&Bs[kk][tx * 4];
            acc[0][0] += av.x * bv.x; acc[0][1] += av.x * bv.y;
            acc[0][2] += av.x * bv.z; acc[0][3] += av.x * bv.w;
            acc[1][0] += av.y * bv.x; acc[1][1] += av.y * bv.y;
            acc[1][2] += av.y * bv.z; acc[1][3] += av.y * bv.w;
            acc[2][0] += av.z * bv.x; acc[2][1] += av.z * bv.y;
            acc[2][2] += av.z * bv.z; acc[2][3] += av.z * bv.w;
            acc[3][0] += av.w * bv.x; acc[3][1] += av.w * bv.y;
            acc[3][2] += av.w * bv.z; acc[3][3] += av.w * bv.w;
        }
        __syncthreads();
    }
#pragma unroll
    for (int r = 0; r < 4; r++) {
        int i = bm + ty * 4 + r;
#pragma unroll
        for (int c = 0; c < 4; c++) {
            int j = bn + tx * 4 + c;
            P[(size_t)i * N + j] = acc[r][c] + bias[j];
        }
    }
}

// ---------------- BN stats: per-column mean/var -> scale/shift ----------------
__global__ void bnstats_kernel(const float* __restrict__ P, int N,
                               const float* __restrict__ g,
                               const float* __restrict__ be,
                               float* __restrict__ sc, float* __restrict__ sh) {
    __shared__ float ss[8][32], sq[8][32];
    int c = blockIdx.x * 32 + threadIdx.x;
    float s = 0.f, q = 0.f;
    for (int r = threadIdx.y; r < BB; r += 8) {
        float v = P[(size_t)r * N + c];
        s += v;
        q += v * v;
    }
    ss[threadIdx.y][threadIdx.x] = s;
    sq[threadIdx.y][threadIdx.x] = q;
    __syncthreads();
    if (threadIdx.y == 0) {
#pragma unroll
        for (int y = 1; y < 8; y++) {
            s += ss[y][threadIdx.x];
            q += sq[y][threadIdx.x];
        }
        float m = s * (1.f / BB);
        float var = q * (1.f / BB) - m * m;
        float a = g[c] * rsqrtf(var + 1e-5f);
        sc[c] = a;
        sh[c] = be[c] - a * m;
    }
}

// ---------------- tree-norm stats ----------------
__global__ void tnstats_kernel(const float* __restrict__ X, int n,
                               float* __restrict__ mean,
                               float* __restrict__ rstd) {
    __shared__ float ss[256], qq[256];
    int b = blockIdx.x;
    int tid = threadIdx.x;
    const float4* p = (const float4*)(X + (size_t)b * n);
    float s = 0.f, q = 0.f;
    for (int i = tid; i < n / 4; i += 256) {
        float4 v = p[i];
        s += v.x + v.y + v.z + v.w;
        q += v.x * v.x + v.y * v.y + v.z * v.z + v.w * v.w;
    }
    ss[tid] = s;
    qq[tid] = q;
    __syncthreads();
    for (int st = 128; st > 0; st >>= 1) {
        if (tid < st) {
            ss[tid] += ss[tid + st];
            qq[tid] += qq[tid + st];
        }
        __syncthreads();
    }
    if (tid == 0) {
        float m = ss[0] / (float)n;
        float var = (qq[0] - (float)n * m * m) / (float)(n - 1);
        var = fmaxf(var, 0.f);
        mean[b] = m;
        rstd[b] = 1.f / (sqrtf(var) + 1e-5f);
    }
}

// ---------------- final tree-norm apply (in-place on d_out) ----------------
__global__ void tnapply_kernel(float* __restrict__ X, int n,
                               const float* __restrict__ mean,
                               const float* __restrict__ rstd) {
    size_t i = (size_t)blockIdx.x * blockDim.x + threadIdx.x;
    size_t total = (size_t)BB * (n / 4);
    if (i >= total) return;
    int b = (int)(i / (n / 4));
    float m = mean[b], r = rstd[b];
    float4* p = (float4*)X;
    float4 v = p[i];
    v.x = (v.x - m) * r; v.x = v.x > 0.f ? v.x : 0.01f * v.x;
    v.y = (v.y - m) * r; v.y = v.y > 0.f ? v.y : 0.01f * v.y;
    v.z = (v.z - m) * r; v.z = v.z > 0.f ? v.z : 0.01f * v.z;
    v.w = (v.w - m) * r; v.w = v.w > 0.f ? v.w : 0.01f * v.w;
    p[i] = v;
}

// ======================= host launch =======================
extern "C" void kernel_launch(void* const* d_in, const int* in_sizes, int n_in,
                              void* d_out, int out_size) {
    const float* trees = (const float*)d_in[0];
    const int* indexes = (const int*)d_in[1];
    const float* w1 = (const float*)d_in[2];
    const float* b1 = (const float*)d_in[3];
    const float* g1 = (const float*)d_in[4];
    const float* be1 = (const float*)d_in[5];
    const float* w2 = (const float*)d_in[6];
    const float* b2 = (const float*)d_in[7];
    const float* g2 = (const float*)d_in[8];
    const float* be2 = (const float*)d_in[9];
    const float* w3 = (const float*)d_in[10];
    const float* b3 = (const float*)d_in[11];
    const float* g3 = (const float*)d_in[12];
    const float* be3 = (const float*)d_in[13];
    const float* w4 = (const float*)d_in[14];
    const float* b4 = (const float*)d_in[15];
    const float* g4 = (const float*)d_in[16];
    const float* be4 = (const float*)d_in[17];
    const float* cw1 = (const float*)d_in[18];
    const float* cb1 = (const float*)d_in[19];
    const float* cw2 = (const float*)d_in[20];
    const float* cb2 = (const float*)d_in[21];
    const float* cw3 = (const float*)d_in[22];
    const float* cb3 = (const float*)d_in[23];
    float* out = (float*)d_out;

    float *p_h1, *p_h2, *p_h3, *p_h4, *p_t1, *p_t2, *p_sc, *p_sh, *p_mean,
        *p_rstd, *p_sA, *p_sB;
    int8_t *p_A1, *p_A2, *p_B1, *p_B2;
    cudaGetSymbolAddress((void**)&p_h1, g_h1);
    cudaGetSymbolAddress((void**)&p_h2, g_h2);
    cudaGetSymbolAddress((void**)&p_h3, g_h3);
    cudaGetSymbolAddress((void**)&p_h4, g_h4);
    cudaGetSymbolAddress((void**)&p_t1, g_t1);
    cudaGetSymbolAddress((void**)&p_t2, g_t2);
    cudaGetSymbolAddress((void**)&p_sc, g_sc);
    cudaGetSymbolAddress((void**)&p_sh, g_sh);
    cudaGetSymbolAddress((void**)&p_mean, g_mean);
    cudaGetSymbolAddress((void**)&p_rstd, g_rstd);
    cudaGetSymbolAddress((void**)&p_sA, g_sA);
    cudaGetSymbolAddress((void**)&p_sB, g_sB);
    cudaGetSymbolAddress((void**)&p_A1, g_A1);
    cudaGetSymbolAddress((void**)&p_A2, g_A2);
    cudaGetSymbolAddress((void**)&p_B1, g_B1);
    cudaGetSymbolAddress((void**)&p_B2, g_B2);

    cudaFuncSetAttribute(imma_gemm<0>, cudaFuncAttributeMaxDynamicSharedMemorySize, GSM_TOTAL);
    cudaFuncSetAttribute(imma_gemm<1>, cudaFuncAttributeMaxDynamicSharedMemorySize, GSM_TOTAL);
    cudaFuncSetAttribute(gather_i8<256, 1>, cudaFuncAttributeMaxDynamicSharedMemorySize, 256 * 64 * 4);

    dim3 bst(32, 8);

    // ---- MLP layer 1 (fp32, tiny) ----
    mlp_gemm0<<<dim3(32, 1), 256>>>(trees, w1, b1, p_h1, 64, 64);
    bnstats_kernel<<<2, bst>>>(p_h1, 64, g1, be1, p_sc, p_sh);

    // ---- MLP layer 2: 2048x256, K=64 (Kp=128) ----
    actsplit_i8<<<BB, 128>>>(p_h1, p_sc, p_sh, p_A1, p_A2, p_sA, 64, 128);
    wsplit_i8<<<256, 128>>>(w2, p_B1, p_B2, p_sB, 64, 128);
    imma_gemm<0><<<dim3(2, 16), 256, GSM_TOTAL>>>(p_A1, p_A2, p_B1, p_B2, p_sA, p_sB, b2, p_h2, 128, 256);
    bnstats_kernel<<<8, bst>>>(p_h2, 256, g2, be2, p_sc, p_sh);

    // ---- MLP layer 3: 2048x1024, K=256 ----
    actsplit_i8<<<BB, 128>>>(p_h2, p_sc, p_sh, p_A1, p_A2, p_sA, 256, 256);
    wsplit_i8<<<1024, 128>>>(w3, p_B1, p_B2, p_sB, 256, 256);
    imma_gemm<0><<<dim3(8, 16), 256, GSM_TOTAL>>>(p_A1, p_A2, p_B1, p_B2, p_sA, p_sB, b3, p_h3, 256, 1024);
    bnstats_kernel<<<32, bst>>>(p_h3, 1024, g3, be3, p_sc, p_sh);

    // ---- MLP layer 4: 2048x4096, K=1024 ----
    actsplit_i8<<<BB, 128>>>(p_h3, p_sc, p_sh, p_A1, p_A2, p_sA, 1024, 1024);
    wsplit_i8<<<4096, 128>>>(w4, p_B1, p_B2, p_sB, 1024, 1024);
    imma_gemm<0><<<dim3(32, 16), 256, GSM_TOTAL>>>(p_A1, p_A2, p_B1, p_B2, p_sA, p_sB, b4, p_h4, 1024, 4096);
    bnstats_kernel<<<128, bst>>>(p_h4, 4096, g4, be4, p_sc, p_sh);

    // ---- tree conv 1: M=129024, N=128, K=192 (Kp=256) ----
    gather_i8<64, 0><<<BB, 256, 64 * 64 * 4>>>(p_h4, indexes, p_sc, p_sh,
                                               nullptr, nullptr, p_A1, p_A2, p_sA, 256);
    wsplit_i8<<<128, 128>>>(cw1, p_B1, p_B2, p_sB, 192, 256);
    imma_gemm<1><<<dim3(1, 1008), 256, GSM_TOTAL>>>(p_A1, p_A2, p_B1, p_B2, p_sA, p_sB, cb1, p_t1, 256, 128);
    tnstats_kernel<<<BB, 256>>>(p_t1, 128 * 64, p_mean, p_rstd);

    // ---- tree conv 2: N=256, K=384 ----
    gather_i8<128, 1><<<BB, 256, 128 * 64 * 4>>>(p_t1, indexes, nullptr, nullptr,
                                                 p_mean, p_rstd, p_A1, p_A2, p_sA, 384);
    wsplit_i8<<<256, 128>>>(cw2, p_B1, p_B2, p_sB, 384, 384);
    imma_gemm<1><<<dim3(2, 1008), 256, GSM_TOTAL>>>(p_A1, p_A2, p_B1, p_B2, p_sA, p_sB, cb2, p_t2, 384, 256);
    tnstats_kernel<<<BB, 256>>>(p_t2, 256 * 64, p_mean, p_rstd);

    // ---- tree conv 3: N=512, K=768 -> d_out ----
    gather_i8<256, 1><<<BB, 256, 256 * 64 * 4>>>(p_t2, indexes, nullptr, nullptr,
                                                 p_mean, p_rstd, p_A1, p_A2, p_sA, 768);
    wsplit_i8<<<512, 128>>>(cw3, p_B1, p_B2, p_sB, 768, 768);
    imma_gemm<1><<<dim3(4, 1008), 256, GSM_TOTAL>>>(p_A1, p_A2, p_B1, p_B2, p_sA, p_sB, cb3, out, 768, 512);
    tnstats_kernel<<<BB, 256>>>(out, 512 * 64, p_mean, p_rstd);
    tnapply_kernel<<<(int)(((size_t)BB * (512 * 64 / 4) + 255) / 256), 256>>>(
        out, 512 * 64, p_mean, p_rstd);
}

// round 12
// speedup vs baseline: 2.3327x; 2.3327x over previous
#include <cuda_runtime.h>
#include <cuda_bf16.h>
#include <cstdint>

#define BB 2048
#define TRIP 189

// ---------------- scratch (device globals: allocation-guard safe) ----------------
__device__ float g_h1[BB * 64];
__device__ float g_h2[BB * 256];
__device__ float g_h3[BB * 1024];
__device__ float g_h4[BB * 4096];
__device__ float g_t1[BB * 128 * 64];
__device__ float g_t2[BB * 256 * 64];
__device__ float g_sc[4096];
__device__ float g_sh[4096];
// split-bf16 operand buffers (reused across layers). Max: 129024 x 768
__device__ __nv_bfloat16 g_Eh[129024 * 768];
__device__ __nv_bfloat16 g_El[129024 * 768];
__device__ __nv_bfloat16 g_Wh[4096 * 1024];
__device__ __nv_bfloat16 g_Wl[4096 * 1024];

// ======================= base-ISA tensor helpers (sm_80+) =======================
__device__ __forceinline__ uint32_t smem_u32(const void* p) {
    uint32_t a;
    asm("{ .reg .u64 t; cvta.to.shared.u64 t, %1; cvt.u32.u64 %0, t; }"
        : "=r"(a) : "l"(p));
    return a;
}
#define LDSM4(r0, r1, r2, r3, addr)                                             \
    asm volatile("ldmatrix.sync.aligned.m8n8.x4.shared.b16 {%0,%1,%2,%3}, [%4];"\
                 : "=r"(r0), "=r"(r1), "=r"(r2), "=r"(r3) : "r"(addr))
#define MMA16816(d, a, b)                                                       \
    asm volatile("mma.sync.aligned.m16n8k16.row.col.f32.bf16.bf16.f32 "         \
                 "{%0,%1,%2,%3}, {%4,%5,%6,%7}, {%8,%9}, {%0,%1,%2,%3};"        \
                 : "+f"((d)[0]), "+f"((d)[1]), "+f"((d)[2]), "+f"((d)[3])       \
                 : "r"((a)[0]), "r"((a)[1]), "r"((a)[2]), "r"((a)[3]),          \
                   "r"((b)[0]), "r"((b)[1]))
#define CP_ASYNC16(dst, src)                                                    \
    asm volatile("cp.async.cg.shared.global [%0], [%1], 16;" :: "r"(dst), "l"(src))
#define CP_COMMIT() asm volatile("cp.async.commit_group;" ::: "memory")
#define CP_WAIT1() asm volatile("cp.async.wait_group 1;" ::: "memory")
#define CP_WAIT0() asm volatile("cp.async.wait_group 0;" ::: "memory")

__device__ __forceinline__ int swz(int off) { return off ^ ((off >> 3) & 0x70); }

// ======================= mma GEMM: C(M,Ntot) = A(M,K) @ B(Ntot,K)^T ============
// split-bf16 3-pass (Ah*Bh + Ah*Bl + Al*Bh). Per K-chunk of 64: load all 4 tiles
// {Ah, Al, Bh, Bl} once (double-buffered), run all 3 passes from smem with
// register-level fragment reuse. Grid = (Ngroups, Mtiles).
// EPI 0: out row-major (M,Ntot), += bias[col]
// EPI 1: conv: row r=(b*63+m); out[b][o][m+1] = v + bias[o]; out[b][o][0] = 0
#define GSM_TOTAL 131072

__device__ __forceinline__ void cp_tile(const __nv_bfloat16* __restrict__ src,
                                        int row0, int K, int kc, uint32_t sdst,
                                        int tid) {
#pragma unroll
    for (int i = 0; i < 4; i++) {
        int lin = tid + i * 256;
        int r = lin >> 3, c16 = (lin & 7) * 16;
        const char* g = (const char*)(src + (size_t)(row0 + r) * K + kc * 64) + c16;
        CP_ASYNC16(sdst + swz(r * 128 + c16), g);
    }
}

template <int EPI>
__global__ __launch_bounds__(256) void mma_gemm(
    const __nv_bfloat16* __restrict__ Ah, const __nv_bfloat16* __restrict__ Al,
    const __nv_bfloat16* __restrict__ Bh, const __nv_bfloat16* __restrict__ Bl,
    const float* __restrict__ bias, float* __restrict__ out, int K, int Ntot) {
    extern __shared__ __align__(1024) char smem[];
    uint32_t sb = smem_u32(smem);
    int tid = threadIdx.x, wid = tid >> 5, lane = tid & 31;
    int bn = blockIdx.x * 128, bm = blockIdx.y * 128;
    int mw = wid >> 1, nw = wid & 1;
    int m_base = mw * 32, n_base = nw * 64;

    const int KC = K >> 6;

    float acc[2][8][4];
#pragma unroll
    for (int mt = 0; mt < 2; mt++)
#pragma unroll
        for (int nt = 0; nt < 8; nt++)
#pragma unroll
            for (int q = 0; q < 4; q++) acc[mt][nt][q] = 0.f;

    int a_row = (lane & 15);
    int a_colsel = (lane & 16) ? 16 : 0;
    int b_row = (lane & 7) + ((lane & 16) ? 8 : 0);
    int b_colsel = (lane & 8) ? 16 : 0;

    {
        uint32_t base = sb;
        cp_tile(Ah, bm, K, 0, base + 0, tid);
        cp_tile(Al, bm, K, 0, base + 16384, tid);
        cp_tile(Bh, bn, K, 0, base + 32768, tid);
        cp_tile(Bl, bn, K, 0, base + 49152, tid);
        CP_COMMIT();
        if (KC > 1) {
            base = sb + 65536;
            cp_tile(Ah, bm, K, 1, base + 0, tid);
            cp_tile(Al, bm, K, 1, base + 16384, tid);
            cp_tile(Bh, bn, K, 1, base + 32768, tid);
            cp_tile(Bl, bn, K, 1, base + 49152, tid);
            CP_COMMIT();
        }
    }

    for (int kc = 0; kc < KC; kc++) {
        int buf = kc & 1;
        if (kc < KC - 1) CP_WAIT1();
        else CP_WAIT0();
        __syncthreads();

        uint32_t base = sb + buf * 65536;
#pragma unroll
        for (int kk = 0; kk < 4; kk++) {
            uint32_t af[2][4];
            uint32_t bh_[8][2];
            uint32_t bl_[8][2];
#pragma unroll
            for (int mt = 0; mt < 2; mt++) {
                int off = (m_base + mt * 16 + a_row) * 128 + kk * 32 + a_colsel;
                LDSM4(af[mt][0], af[mt][1], af[mt][2], af[mt][3],
                      base + 0 + swz(off));
            }
#pragma unroll
            for (int np = 0; np < 4; np++) {
                int off = (n_base + np * 16 + b_row) * 128 + kk * 32 + b_colsel;
                LDSM4(bh_[2 * np][0], bh_[2 * np][1], bh_[2 * np + 1][0],
                      bh_[2 * np + 1][1], base + 32768 + swz(off));
            }
#pragma unroll
            for (int mt = 0; mt < 2; mt++)
#pragma unroll
                for (int nt = 0; nt < 8; nt++) MMA16816(acc[mt][nt], af[mt], bh_[nt]);
#pragma unroll
            for (int np = 0; np < 4; np++) {
                int off = (n_base + np * 16 + b_row) * 128 + kk * 32 + b_colsel;
                LDSM4(bl_[2 * np][0], bl_[2 * np][1], bl_[2 * np + 1][0],
                      bl_[2 * np + 1][1], base + 49152 + swz(off));
            }
#pragma unroll
            for (int mt = 0; mt < 2; mt++)
#pragma unroll
                for (int nt = 0; nt < 8; nt++) MMA16816(acc[mt][nt], af[mt], bl_[nt]);
#pragma unroll
            for (int mt = 0; mt < 2; mt++) {
                int off = (m_base + mt * 16 + a_row) * 128 + kk * 32 + a_colsel;
                LDSM4(af[mt][0], af[mt][1], af[mt][2], af[mt][3],
                      base + 16384 + swz(off));
            }
#pragma unroll
            for (int mt = 0; mt < 2; mt++)
#pragma unroll
                for (int nt = 0; nt < 8; nt++) MMA16816(acc[mt][nt], af[mt], bh_[nt]);
        }
        __syncthreads();
        if (kc + 2 < KC) {
            int cn = kc + 2;
            uint32_t pb = sb + buf * 65536;
            cp_tile(Ah, bm, K, cn, pb + 0, tid);
            cp_tile(Al, bm, K, cn, pb + 16384, tid);
            cp_tile(Bh, bn, K, cn, pb + 32768, tid);
            cp_tile(Bl, bn, K, cn, pb + 49152, tid);
            CP_COMMIT();
        }
    }

    // ---------------- epilogue ----------------
    if (EPI == 0) {
#pragma unroll
        for (int mt = 0; mt < 2; mt++) {
            int r0 = bm + m_base + mt * 16 + (lane >> 2);
#pragma unroll
            for (int nt = 0; nt < 8; nt++) {
                int cidx = bn + n_base + nt * 8 + (lane & 3) * 2;
                float bx = __ldg(&bias[cidx]), by = __ldg(&bias[cidx + 1]);
                float2 v0 = {acc[mt][nt][0] + bx, acc[mt][nt][1] + by};
                float2 v1 = {acc[mt][nt][2] + bx, acc[mt][nt][3] + by};
                *(float2*)(out + (size_t)r0 * Ntot + cidx) = v0;
                *(float2*)(out + (size_t)(r0 + 8) * Ntot + cidx) = v1;
            }
        }
    } else {
        const int PAD = 129;
        float* S = (float*)smem;
        __syncthreads();
#pragma unroll
        for (int mt = 0; mt < 2; mt++) {
            int r0 = m_base + mt * 16 + (lane >> 2);
#pragma unroll
            for (int nt = 0; nt < 8; nt++) {
                int cidx = n_base + nt * 8 + (lane & 3) * 2;
                S[r0 * PAD + cidx] = acc[mt][nt][0];
                S[r0 * PAD + cidx + 1] = acc[mt][nt][1];
                S[(r0 + 8) * PAD + cidx] = acc[mt][nt][2];
                S[(r0 + 8) * PAD + cidx + 1] = acc[mt][nt][3];
            }
        }
        __syncthreads();
        for (int e = tid; e < 128 * 128; e += 256) {
            int o = e >> 7;
            int lr = e & 127;
            int r = bm + lr;
            int b = r / 63;
            int m = r - b * 63;
            int oo = bn + o;
            float v = S[lr * PAD + o] + __ldg(&bias[oo]);
            float* ob = out + (size_t)b * Ntot * 64 + (size_t)oo * 64;
            ob[m + 1] = v;
            if (m == 0) ob[0] = 0.f;
        }
    }
}

// ======================= prep kernels =======================
__global__ void wsplit_kernel(const float* __restrict__ w,
                              __nv_bfloat16* __restrict__ wh,
                              __nv_bfloat16* __restrict__ wl, int n) {
    int i = blockIdx.x * 256 + threadIdx.x;
    if (i >= n) return;
    float v = w[i];
    __nv_bfloat16 h = __float2bfloat16(v);
    wh[i] = h;
    wl[i] = __float2bfloat16(v - __bfloat162float(h));
}

__global__ void actsplit_kernel(const float* __restrict__ in,
                                const float* __restrict__ sc,
                                const float* __restrict__ sh,
                                __nv_bfloat16* __restrict__ ah,
                                __nv_bfloat16* __restrict__ al, int Kmask, int n) {
    int i = blockIdx.x * 256 + threadIdx.x;
    if (i >= n) return;
    int c = i & Kmask;
    float v = fmaf(sc[c], in[i], sh[c]);
    v = v > 0.f ? v : 0.01f * v;
    __nv_bfloat16 h = __float2bfloat16(v);
    ah[i] = h;
    al[i] = __float2bfloat16(v - __bfloat162float(h));
}

// gather + normalize + lrelu + bf16 split -> E(b*63+m, 3*CIN)
// MODE 0: per-feature affine sc/sh. MODE 1: per-sample tree-norm, with the
// mean/unbiased-std computed IN-BLOCK from the smem-staged x[b] (fused tnstats).
template <int CIN, int MODE>
__global__ __launch_bounds__(256) void gather_kernel(
    const float* __restrict__ in, const int* __restrict__ idx,
    const float* __restrict__ sc, const float* __restrict__ sh,
    __nv_bfloat16* __restrict__ Eh, __nv_bfloat16* __restrict__ El) {
    extern __shared__ float xs[];
    __shared__ int sidx[TRIP];
    __shared__ float rs[256], rq[256];
    const int K = 3 * CIN;
    const int NEL = CIN * 64;
    int b = blockIdx.x, tid = threadIdx.x;
    for (int j = tid; j < TRIP; j += 256) sidx[j] = idx[b * TRIP + j];
    const float* xb = in + (size_t)b * NEL;
    if (MODE == 0) {
        for (int i = tid; i < NEL; i += 256) {
            float v = fmaf(__ldg(&sc[i]), xb[i], __ldg(&sh[i]));
            v = v > 0.f ? v : 0.01f * v;
            xs[i] = v;
        }
        __syncthreads();
    } else {
        float s = 0.f, q = 0.f;
        for (int i = tid; i < NEL; i += 256) {
            float v = xb[i];
            xs[i] = v;
            s += v;
            q += v * v;
        }
        rs[tid] = s;
        rq[tid] = q;
        __syncthreads();
        for (int st = 128; st > 0; st >>= 1) {
            if (tid < st) {
                rs[tid] += rs[tid + st];
                rq[tid] += rq[tid + st];
            }
            __syncthreads();
        }
        float m = rs[0] / (float)NEL;
        float var = (rq[0] - (float)NEL * m * m) / (float)(NEL - 1);
        var = fmaxf(var, 0.f);
        float r = 1.f / (sqrtf(var) + 1e-5f);
        for (int i = tid; i < NEL; i += 256) {
            float v = (xs[i] - m) * r;
            xs[i] = v > 0.f ? v : 0.01f * v;
        }
        __syncthreads();
    }
    const int KH = K >> 1;
    __nv_bfloat162* EH = (__nv_bfloat162*)Eh;
    __nv_bfloat162* EL = (__nv_bfloat162*)El;
    for (int f = tid; f < 63 * KH; f += 256) {
        int m = f / KH;
        int t = (f - m * KH) * 2;
        int c0 = t / 3, k0 = t - 3 * c0;
        int t1 = t + 1;
        int c1 = t1 / 3, k1 = t1 - 3 * c1;
        float e0 = xs[c0 * 64 + sidx[3 * m + k0]];
        float e1 = xs[c1 * 64 + sidx[3 * m + k1]];
        __nv_bfloat16 h0 = __float2bfloat16(e0), h1 = __float2bfloat16(e1);
        float l0 = e0 - __bfloat162float(h0);
        float l1 = e1 - __bfloat162float(h1);
        size_t off = ((size_t)(b * 63 + m) * K + t) >> 1;
        EH[off] = __halves2bfloat162(h0, h1);
        EL[off] = __halves2bfloat162(__float2bfloat16(l0), __float2bfloat16(l1));
    }
}

// ======================= fp32 MLP layer-1 GEMM (tiny) =======================
__global__ __launch_bounds__(256) void mlp_gemm0(
    const float* __restrict__ A, const float* __restrict__ W,
    const float* __restrict__ bias, float* __restrict__ P, int K, int N) {
    __shared__ float As[16][64];
    __shared__ float Bs[16][64];
    int tid = threadIdx.x;
    int bm = blockIdx.x * 64, bn = blockIdx.y * 64;
    int lr = tid >> 2, lk = (tid & 3) * 4;
    int tx = tid & 15, ty = tid >> 4;
    float acc[4][4];
#pragma unroll
    for (int r = 0; r < 4; r++)
#pragma unroll
        for (int c = 0; c < 4; c++) acc[r][c] = 0.f;
    for (int k0 = 0; k0 < K; k0 += 16) {
        float4 a = *(const float4*)(A + (size_t)(bm + lr) * K + k0 + lk);
        float4 w4 = *(const float4*)(W + (size_t)(bn + lr) * K + k0 + lk);
        As[lk + 0][lr] = a.x; As[lk + 1][lr] = a.y;
        As[lk + 2][lr] = a.z; As[lk + 3][lr] = a.w;
        Bs[lk + 0][lr] = w4.x; Bs[lk + 1][lr] = w4.y;
        Bs[lk + 2][lr] = w4.z; Bs[lk + 3][lr] = w4.w;
        __syncthreads();
#pragma unroll
        for (int kk = 0; kk < 16; kk++) {
            float4 av = *(const float4*)&As[kk][ty * 4];
            float4 bv = *(const float4*)&Bs[kk][tx * 4];
            acc[0][0] += av.x * bv.x; acc[0][1] += av.x * bv.y;
            acc[0][2] += av.x * bv.z; acc[0][3] += av.x * bv.w;
            acc[1][0] += av.y * bv.x; acc[1][1] += av.y * bv.y;
            acc[1][2] += av.y * bv.z; acc[1][3] += av.y * bv.w;
            acc[2][0] += av.z * bv.x; acc[2][1] += av.z * bv.y;
            acc[2][2] += av.z * bv.z; acc[2][3] += av.z * bv.w;
            acc[3][0] += av.w * bv.x; acc[3][1] += av.w * bv.y;
            acc[3][2] += av.w * bv.z; acc[3][3] += av.w * bv.w;
        }
        __syncthreads();
    }
#pragma unroll
    for (int r = 0; r < 4; r++) {
        int i = bm + ty * 4 + r;
#pragma unroll
        for (int c = 0; c < 4; c++) {
            int j = bn + tx * 4 + c;
            P[(size_t)i * N + j] = acc[r][c] + bias[j];
        }
    }
}

// ---------------- BN stats: per-column mean/var -> scale/shift ----------------
__global__ void bnstats_kernel(const float* __restrict__ P, int N,
                               const float* __restrict__ g,
                               const float* __restrict__ be,
                               float* __restrict__ sc, float* __restrict__ sh) {
    __shared__ float ss[8][32], sq[8][32];
    int c = blockIdx.x * 32 + threadIdx.x;
    float s = 0.f, q = 0.f;
    for (int r = threadIdx.y; r < BB; r += 8) {
        float v = P[(size_t)r * N + c];
        s += v;
        q += v * v;
    }
    ss[threadIdx.y][threadIdx.x] = s;
    sq[threadIdx.y][threadIdx.x] = q;
    __syncthreads();
    if (threadIdx.y == 0) {
#pragma unroll
        for (int y = 1; y < 8; y++) {
            s += ss[y][threadIdx.x];
            q += sq[y][threadIdx.x];
        }
        float m = s * (1.f / BB);
        float var = q * (1.f / BB) - m * m;
        float a = g[c] * rsqrtf(var + 1e-5f);
        sc[c] = a;
        sh[c] = be[c] - a * m;
    }
}

// ---------------- final fused tree-norm: stats + apply + lrelu, smem-staged ----
// one block per sample; n = 512*64 floats = 128KB smem
__global__ __launch_bounds__(256) void tnfinal_kernel(float* __restrict__ X, int n) {
    extern __shared__ float s[];
    __shared__ float rs[256], rq[256];
    int b = blockIdx.x, tid = threadIdx.x;
    float4* src = (float4*)(X + (size_t)b * n);
    float4* sv = (float4*)s;
    float ss = 0.f, qq = 0.f;
    int n4 = n >> 2;
    for (int i = tid; i < n4; i += 256) {
        float4 v = src[i];
        sv[i] = v;
        ss += v.x + v.y + v.z + v.w;
        qq += v.x * v.x + v.y * v.y + v.z * v.z + v.w * v.w;
    }
    rs[tid] = ss;
    rq[tid] = qq;
    __syncthreads();
    for (int st = 128; st > 0; st >>= 1) {
        if (tid < st) {
            rs[tid] += rs[tid + st];
            rq[tid] += rq[tid + st];
        }
        __syncthreads();
    }
    float m = rs[0] / (float)n;
    float var = (rq[0] - (float)n * m * m) / (float)(n - 1);
    var = fmaxf(var, 0.f);
    float r = 1.f / (sqrtf(var) + 1e-5f);
    for (int i = tid; i < n4; i += 256) {
        float4 v = sv[i];
        v.x = (v.x - m) * r; v.x = v.x > 0.f ? v.x : 0.01f * v.x;
        v.y = (v.y - m) * r; v.y = v.y > 0.f ? v.y : 0.01f * v.y;
        v.z = (v.z - m) * r; v.z = v.z > 0.f ? v.z : 0.01f * v.z;
        v.w = (v.w - m) * r; v.w = v.w > 0.f ? v.w : 0.01f * v.w;
        src[i] = v;
    }
}

// ======================= host launch =======================
extern "C" void kernel_launch(void* const* d_in, const int* in_sizes, int n_in,
                              void* d_out, int out_size) {
    const float* trees = (const float*)d_in[0];
    const int* indexes = (const int*)d_in[1];
    const float* w1 = (const float*)d_in[2];
    const float* b1 = (const float*)d_in[3];
    const float* g1 = (const float*)d_in[4];
    const float* be1 = (const float*)d_in[5];
    const float* w2 = (const float*)d_in[6];
    const float* b2 = (const float*)d_in[7];
    const float* g2 = (const float*)d_in[8];
    const float* be2 = (const float*)d_in[9];
    const float* w3 = (const float*)d_in[10];
    const float* b3 = (const float*)d_in[11];
    const float* g3 = (const float*)d_in[12];
    const float* be3 = (const float*)d_in[13];
    const float* w4 = (const float*)d_in[14];
    const float* b4 = (const float*)d_in[15];
    const float* g4 = (const float*)d_in[16];
    const float* be4 = (const float*)d_in[17];
    const float* cw1 = (const float*)d_in[18];
    const float* cb1 = (const float*)d_in[19];
    const float* cw2 = (const float*)d_in[20];
    const float* cb2 = (const float*)d_in[21];
    const float* cw3 = (const float*)d_in[22];
    const float* cb3 = (const float*)d_in[23];
    float* out = (float*)d_out;

    float *p_h1, *p_h2, *p_h3, *p_h4, *p_t1, *p_t2, *p_sc, *p_sh;
    __nv_bfloat16 *p_Eh, *p_El, *p_Wh, *p_Wl;
    cudaGetSymbolAddress((void**)&p_h1, g_h1);
    cudaGetSymbolAddress((void**)&p_h2, g_h2);
    cudaGetSymbolAddress((void**)&p_h3, g_h3);
    cudaGetSymbolAddress((void**)&p_h4, g_h4);
    cudaGetSymbolAddress((void**)&p_t1, g_t1);
    cudaGetSymbolAddress((void**)&p_t2, g_t2);
    cudaGetSymbolAddress((void**)&p_sc, g_sc);
    cudaGetSymbolAddress((void**)&p_sh, g_sh);
    cudaGetSymbolAddress((void**)&p_Eh, g_Eh);
    cudaGetSymbolAddress((void**)&p_El, g_El);
    cudaGetSymbolAddress((void**)&p_Wh, g_Wh);
    cudaGetSymbolAddress((void**)&p_Wl, g_Wl);

    cudaFuncSetAttribute(mma_gemm<0>, cudaFuncAttributeMaxDynamicSharedMemorySize, GSM_TOTAL);
    cudaFuncSetAttribute(mma_gemm<1>, cudaFuncAttributeMaxDynamicSharedMemorySize, GSM_TOTAL);
    cudaFuncSetAttribute(gather_kernel<256, 1>, cudaFuncAttributeMaxDynamicSharedMemorySize, 256 * 64 * 4);
    cudaFuncSetAttribute(tnfinal_kernel, cudaFuncAttributeMaxDynamicSharedMemorySize, 512 * 64 * 4);

    dim3 bst(32, 8);

    // ---- MLP layer 1 (fp32, tiny) ----
    mlp_gemm0<<<dim3(32, 1), 256>>>(trees, w1, b1, p_h1, 64, 64);
    bnstats_kernel<<<2, bst>>>(p_h1, 64, g1, be1, p_sc, p_sh);

    // ---- MLP layer 2: 2048x256, K=64 ----
    actsplit_kernel<<<(BB * 64 + 255) / 256, 256>>>(p_h1, p_sc, p_sh, p_Eh, p_El, 63, BB * 64);
    wsplit_kernel<<<(256 * 64 + 255) / 256, 256>>>(w2, p_Wh, p_Wl, 256 * 64);
    mma_gemm<0><<<dim3(2, 16), 256, GSM_TOTAL>>>(p_Eh, p_El, p_Wh, p_Wl, b2, p_h2, 64, 256);
    bnstats_kernel<<<8, bst>>>(p_h2, 256, g2, be2, p_sc, p_sh);

    // ---- MLP layer 3: 2048x1024, K=256 ----
    actsplit_kernel<<<(BB * 256 + 255) / 256, 256>>>(p_h2, p_sc, p_sh, p_Eh, p_El, 255, BB * 256);
    wsplit_kernel<<<(1024 * 256 + 255) / 256, 256>>>(w3, p_Wh, p_Wl, 1024 * 256);
    mma_gemm<0><<<dim3(8, 16), 256, GSM_TOTAL>>>(p_Eh, p_El, p_Wh, p_Wl, b3, p_h3, 256, 1024);
    bnstats_kernel<<<32, bst>>>(p_h3, 1024, g3, be3, p_sc, p_sh);

    // ---- MLP layer 4: 2048x4096, K=1024 ----
    actsplit_kernel<<<(BB * 1024 + 255) / 256, 256>>>(p_h3, p_sc, p_sh, p_Eh, p_El, 1023, BB * 1024);
    wsplit_kernel<<<(4096 * 1024 + 255) / 256, 256>>>(w4, p_Wh, p_Wl, 4096 * 1024);
    mma_gemm<0><<<dim3(32, 16), 256, GSM_TOTAL>>>(p_Eh, p_El, p_Wh, p_Wl, b4, p_h4, 1024, 4096);
    bnstats_kernel<<<128, bst>>>(p_h4, 4096, g4, be4, p_sc, p_sh);

    // ---- tree conv 1: M=129024, N=128, K=192 ----
    gather_kernel<64, 0><<<BB, 256, 64 * 64 * 4>>>(p_h4, indexes, p_sc, p_sh, p_Eh, p_El);
    wsplit_kernel<<<(128 * 192 + 255) / 256, 256>>>(cw1, p_Wh, p_Wl, 128 * 192);
    mma_gemm<1><<<dim3(1, 1008), 256, GSM_TOTAL>>>(p_Eh, p_El, p_Wh, p_Wl, cb1, p_t1, 192, 128);

    // ---- tree conv 2: N=256, K=384 (tree-norm of t1 fused into gather) ----
    gather_kernel<128, 1><<<BB, 256, 128 * 64 * 4>>>(p_t1, indexes, nullptr, nullptr, p_Eh, p_El);
    wsplit_kernel<<<(256 * 384 + 255) / 256, 256>>>(cw2, p_Wh, p_Wl, 256 * 384);
    mma_gemm<1><<<dim3(2, 1008), 256, GSM_TOTAL>>>(p_Eh, p_El, p_Wh, p_Wl, cb2, p_t2, 384, 256);

    // ---- tree conv 3: N=512, K=768 -> d_out (tree-norm of t2 fused into gather) ----
    gather_kernel<256, 1><<<BB, 256, 256 * 64 * 4>>>(p_t2, indexes, nullptr, nullptr, p_Eh, p_El);
    wsplit_kernel<<<(512 * 768 + 255) / 256, 256>>>(cw3, p_Wh, p_Wl, 512 * 768);
    mma_gemm<1><<<dim3(4, 1008), 256, GSM_TOTAL>>>(p_Eh, p_El, p_Wh, p_Wl, cb3, out, 768, 512);

    // ---- final tree-norm + lrelu, fused single pass ----
    tnfinal_kernel<<<BB, 256, 512 * 64 * 4>>>(out, 512 * 64);
}

// round 14
// speedup vs baseline: 2.3970x; 1.0276x over previous
#include <cuda_runtime.h>
#include <cuda_bf16.h>
#include <cstdint>

#define BB 2048
#define TRIP 189

// ---------------- scratch (device globals: allocation-guard safe) ----------------
__device__ float g_h1[BB * 64];
__device__ float g_h2[BB * 256];
__device__ float g_h3[BB * 1024];
__device__ float g_h4[BB * 4096];
__device__ float g_t1[BB * 128 * 64];
__device__ float g_t2[BB * 256 * 64];
__device__ float g_sc[4096];
__device__ float g_sh[4096];
// split-bf16 operand buffers (reused across layers). Max: 129024 x 768
__device__ __nv_bfloat16 g_Eh[129024 * 768];
__device__ __nv_bfloat16 g_El[129024 * 768];
__device__ __nv_bfloat16 g_Wh[4096 * 1024];
__device__ __nv_bfloat16 g_Wl[4096 * 1024];

// ======================= base-ISA tensor helpers (sm_80+) =======================
__device__ __forceinline__ uint32_t smem_u32(const void* p) {
    uint32_t a;
    asm("{ .reg .u64 t; cvta.to.shared.u64 t, %1; cvt.u32.u64 %0, t; }"
        : "=r"(a) : "l"(p));
    return a;
}
#define LDSM4(r0, r1, r2, r3, addr)                                             \
    asm volatile("ldmatrix.sync.aligned.m8n8.x4.shared.b16 {%0,%1,%2,%3}, [%4];"\
                 : "=r"(r0), "=r"(r1), "=r"(r2), "=r"(r3) : "r"(addr))
#define MMA16816(d, a, b)                                                       \
    asm volatile("mma.sync.aligned.m16n8k16.row.col.f32.bf16.bf16.f32 "         \
                 "{%0,%1,%2,%3}, {%4,%5,%6,%7}, {%8,%9}, {%0,%1,%2,%3};"        \
                 : "+f"((d)[0]), "+f"((d)[1]), "+f"((d)[2]), "+f"((d)[3])       \
                 : "r"((a)[0]), "r"((a)[1]), "r"((a)[2]), "r"((a)[3]),          \
                   "r"((b)[0]), "r"((b)[1]))
#define CP_ASYNC16(dst, src)                                                    \
    asm volatile("cp.async.cg.shared.global [%0], [%1], 16;" :: "r"(dst), "l"(src))
#define CP_COMMIT() asm volatile("cp.async.commit_group;" ::: "memory")
#define CP_WAIT1() asm volatile("cp.async.wait_group 1;" ::: "memory")
#define CP_WAIT0() asm volatile("cp.async.wait_group 0;" ::: "memory")

__device__ __forceinline__ int swz(int off) { return off ^ ((off >> 3) & 0x70); }

// ======================= mma GEMM: C(M,Ntot) = A(M,K) @ B(Ntot,K)^T ============
// split-bf16 3-pass (Ah*Bh + Ah*Bl + Al*Bh). CTA tile 256x128, warp tile 64x64
// (4Mx2N warp grid) -> 85.3 smem-bytes per MMA (vs 128 at 32x64 warps).
// Per K-chunk of 64: load {Ah(256x64), Al, Bh(128x64), Bl} once, double-buffered
// (2 x 96KB smem), run all 3 passes from smem with register fragment reuse.
// Buffer layout: Ah@0(32K) Al@32768 Bh@65536(16K) Bl@81920; stride 98304.
// EPI 0: out row-major (M,Ntot), += bias[col]
// EPI 1: conv: row r=(b*63+m); out[b][o][m+1] = v + bias[o]; out[b][o][0] = 0
#define GSM_TOTAL 196608

template <int ROWS>
__device__ __forceinline__ void cp_tileT(const __nv_bfloat16* __restrict__ src,
                                         int row0, int K, int kc, uint32_t sdst,
                                         int tid) {
#pragma unroll
    for (int i = 0; i < ROWS / 32; i++) {
        int lin = tid + i * 256;
        int r = lin >> 3, c16 = (lin & 7) * 16;
        const char* g = (const char*)(src + (size_t)(row0 + r) * K + kc * 64) + c16;
        CP_ASYNC16(sdst + swz(r * 128 + c16), g);
    }
}

__device__ __forceinline__ void load_chunk(const __nv_bfloat16* Ah,
                                           const __nv_bfloat16* Al,
                                           const __nv_bfloat16* Bh,
                                           const __nv_bfloat16* Bl, int bm, int bn,
                                           int K, int kc, uint32_t base, int tid) {
    cp_tileT<256>(Ah, bm, K, kc, base + 0, tid);
    cp_tileT<256>(Al, bm, K, kc, base + 32768, tid);
    cp_tileT<128>(Bh, bn, K, kc, base + 65536, tid);
    cp_tileT<128>(Bl, bn, K, kc, base + 81920, tid);
    CP_COMMIT();
}

template <int EPI>
__global__ __launch_bounds__(256) void mma_gemm(
    const __nv_bfloat16* __restrict__ Ah, const __nv_bfloat16* __restrict__ Al,
    const __nv_bfloat16* __restrict__ Bh, const __nv_bfloat16* __restrict__ Bl,
    const float* __restrict__ bias, float* __restrict__ out, int K, int Ntot) {
    extern __shared__ __align__(1024) char smem[];
    uint32_t sb = smem_u32(smem);
    int tid = threadIdx.x, wid = tid >> 5, lane = tid & 31;
    int bn = blockIdx.x * 128, bm = blockIdx.y * 256;
    int mw = wid >> 1, nw = wid & 1;  // warp grid 4 (M) x 2 (N)
    int m_base = mw * 64, n_base = nw * 64;

    const int KC = K >> 6;

    float acc[4][8][4];
#pragma unroll
    for (int mt = 0; mt < 4; mt++)
#pragma unroll
        for (int nt = 0; nt < 8; nt++)
#pragma unroll
            for (int q = 0; q < 4; q++) acc[mt][nt][q] = 0.f;

    int a_row = (lane & 15);
    int a_colsel = (lane & 16) ? 16 : 0;
    int b_row = (lane & 7) + ((lane & 16) ? 8 : 0);
    int b_colsel = (lane & 8) ? 16 : 0;

    load_chunk(Ah, Al, Bh, Bl, bm, bn, K, 0, sb, tid);
    if (KC > 1) load_chunk(Ah, Al, Bh, Bl, bm, bn, K, 1, sb + 98304, tid);

    for (int kc = 0; kc < KC; kc++) {
        int buf = kc & 1;
        if (kc < KC - 1) CP_WAIT1();
        else CP_WAIT0();
        __syncthreads();

        uint32_t base = sb + buf * 98304;
#pragma unroll
        for (int kk = 0; kk < 4; kk++) {
            uint32_t af[4][4];
            uint32_t bh_[8][2];
            uint32_t bl_[8][2];
            // load A-hi + B-hi, pass 0: Ah*Bh
#pragma unroll
            for (int mt = 0; mt < 4; mt++) {
                int off = (m_base + mt * 16 + a_row) * 128 + kk * 32 + a_colsel;
                LDSM4(af[mt][0], af[mt][1], af[mt][2], af[mt][3],
                      base + 0 + swz(off));
            }
#pragma unroll
            for (int np = 0; np < 4; np++) {
                int off = (n_base + np * 16 + b_row) * 128 + kk * 32 + b_colsel;
                LDSM4(bh_[2 * np][0], bh_[2 * np][1], bh_[2 * np + 1][0],
                      bh_[2 * np + 1][1], base + 65536 + swz(off));
            }
#pragma unroll
            for (int mt = 0; mt < 4; mt++)
#pragma unroll
                for (int nt = 0; nt < 8; nt++) MMA16816(acc[mt][nt], af[mt], bh_[nt]);
            // load B-lo, pass 1: Ah*Bl (reuse af)
#pragma unroll
            for (int np = 0; np < 4; np++) {
                int off = (n_base + np * 16 + b_row) * 128 + kk * 32 + b_colsel;
                LDSM4(bl_[2 * np][0], bl_[2 * np][1], bl_[2 * np + 1][0],
                      bl_[2 * np + 1][1], base + 81920 + swz(off));
            }
#pragma unroll
            for (int mt = 0; mt < 4; mt++)
#pragma unroll
                for (int nt = 0; nt < 8; nt++) MMA16816(acc[mt][nt], af[mt], bl_[nt]);
            // load A-lo into af, pass 2: Al*Bh (reuse bh_)
#pragma unroll
            for (int mt = 0; mt < 4; mt++) {
                int off = (m_base + mt * 16 + a_row) * 128 + kk * 32 + a_colsel;
                LDSM4(af[mt][0], af[mt][1], af[mt][2], af[mt][3],
                      base + 32768 + swz(off));
            }
#pragma unroll
            for (int mt = 0; mt < 4; mt++)
#pragma unroll
                for (int nt = 0; nt < 8; nt++) MMA16816(acc[mt][nt], af[mt], bh_[nt]);
        }
        __syncthreads();
        if (kc + 2 < KC)
            load_chunk(Ah, Al, Bh, Bl, bm, bn, K, kc + 2, sb + buf * 98304, tid);
    }

    // ---------------- epilogue ----------------
    if (EPI == 0) {
#pragma unroll
        for (int mt = 0; mt < 4; mt++) {
            int r0 = bm + m_base + mt * 16 + (lane >> 2);
#pragma unroll
            for (int nt = 0; nt < 8; nt++) {
                int cidx = bn + n_base + nt * 8 + (lane & 3) * 2;
                float bx = __ldg(&bias[cidx]), by = __ldg(&bias[cidx + 1]);
                float2 v0 = {acc[mt][nt][0] + bx, acc[mt][nt][1] + by};
                float2 v1 = {acc[mt][nt][2] + bx, acc[mt][nt][3] + by};
                *(float2*)(out + (size_t)r0 * Ntot + cidx) = v0;
                *(float2*)(out + (size_t)(r0 + 8) * Ntot + cidx) = v1;
            }
        }
    } else {
        const int PAD = 129;
        float* S = (float*)smem;
        __syncthreads();
#pragma unroll
        for (int mt = 0; mt < 4; mt++) {
            int r0 = m_base + mt * 16 + (lane >> 2);
#pragma unroll
            for (int nt = 0; nt < 8; nt++) {
                int cidx = n_base + nt * 8 + (lane & 3) * 2;
                S[r0 * PAD + cidx] = acc[mt][nt][0];
                S[r0 * PAD + cidx + 1] = acc[mt][nt][1];
                S[(r0 + 8) * PAD + cidx] = acc[mt][nt][2];
                S[(r0 + 8) * PAD + cidx + 1] = acc[mt][nt][3];
            }
        }
        __syncthreads();
        for (int e = tid; e < 256 * 128; e += 256) {
            int o = e >> 8;       // 0..127
            int lr = e & 255;     // consecutive tid -> consecutive rows
            int r = bm + lr;
            int b = r / 63;
            int m = r - b * 63;
            int oo = bn + o;
            float v = S[lr * PAD + o] + __ldg(&bias[oo]);
            float* ob = out + (size_t)b * Ntot * 64 + (size_t)oo * 64;
            ob[m + 1] = v;
            if (m == 0) ob[0] = 0.f;
        }
    }
}

// ======================= prep kernels =======================
__global__ void wsplit_kernel(const float* __restrict__ w,
                              __nv_bfloat16* __restrict__ wh,
                              __nv_bfloat16* __restrict__ wl, int n) {
    int i = blockIdx.x * 256 + threadIdx.x;
    if (i >= n) return;
    float v = w[i];
    __nv_bfloat16 h = __float2bfloat16(v);
    wh[i] = h;
    wl[i] = __float2bfloat16(v - __bfloat162float(h));
}

__global__ void actsplit_kernel(const float* __restrict__ in,
                                const float* __restrict__ sc,
                                const float* __restrict__ sh,
                                __nv_bfloat16* __restrict__ ah,
                                __nv_bfloat16* __restrict__ al, int Kmask, int n) {
    int i = blockIdx.x * 256 + threadIdx.x;
    if (i >= n) return;
    int c = i & Kmask;
    float v = fmaf(sc[c], in[i], sh[c]);
    v = v > 0.f ? v : 0.01f * v;
    __nv_bfloat16 h = __float2bfloat16(v);
    ah[i] = h;
    al[i] = __float2bfloat16(v - __bfloat162float(h));
}

// gather + normalize + lrelu + bf16 split -> E(b*63+m, 3*CIN)
// MODE 0: per-feature affine sc/sh. MODE 1: per-sample tree-norm, with the
// mean/unbiased-std computed IN-BLOCK from the smem-staged x[b] (fused tnstats).
template <int CIN, int MODE>
__global__ __launch_bounds__(256) void gather_kernel(
    const float* __restrict__ in, const int* __restrict__ idx,
    const float* __restrict__ sc, const float* __restrict__ sh,
    __nv_bfloat16* __restrict__ Eh, __nv_bfloat16* __restrict__ El) {
    extern __shared__ float xs[];
    __shared__ int sidx[TRIP];
    __shared__ float rs[256], rq[256];
    const int K = 3 * CIN;
    const int NEL = CIN * 64;
    int b = blockIdx.x, tid = threadIdx.x;
    for (int j = tid; j < TRIP; j += 256) sidx[j] = idx[b * TRIP + j];
    const float* xb = in + (size_t)b * NEL;
    if (MODE == 0) {
        for (int i = tid; i < NEL; i += 256) {
            float v = fmaf(__ldg(&sc[i]), xb[i], __ldg(&sh[i]));
            v = v > 0.f ? v : 0.01f * v;
            xs[i] = v;
        }
        __syncthreads();
    } else {
        float s = 0.f, q = 0.f;
        for (int i = tid; i < NEL; i += 256) {
            float v = xb[i];
            xs[i] = v;
            s += v;
            q += v * v;
        }
        rs[tid] = s;
        rq[tid] = q;
        __syncthreads();
        for (int st = 128; st > 0; st >>= 1) {
            if (tid < st) {
                rs[tid] += rs[tid + st];
                rq[tid] += rq[tid + st];
            }
            __syncthreads();
        }
        float m = rs[0] / (float)NEL;
        float var = (rq[0] - (float)NEL * m * m) / (float)(NEL - 1);
        var = fmaxf(var, 0.f);
        float r = 1.f / (sqrtf(var) + 1e-5f);
        for (int i = tid; i < NEL; i += 256) {
            float v = (xs[i] - m) * r;
            xs[i] = v > 0.f ? v : 0.01f * v;
        }
        __syncthreads();
    }
    const int KH = K >> 1;
    __nv_bfloat162* EH = (__nv_bfloat162*)Eh;
    __nv_bfloat162* EL = (__nv_bfloat162*)El;
    for (int f = tid; f < 63 * KH; f += 256) {
        int m = f / KH;
        int t = (f - m * KH) * 2;
        int c0 = t / 3, k0 = t - 3 * c0;
        int t1 = t + 1;
        int c1 = t1 / 3, k1 = t1 - 3 * c1;
        float e0 = xs[c0 * 64 + sidx[3 * m + k0]];
        float e1 = xs[c1 * 64 + sidx[3 * m + k1]];
        __nv_bfloat16 h0 = __float2bfloat16(e0), h1 = __float2bfloat16(e1);
        float l0 = e0 - __bfloat162float(h0);
        float l1 = e1 - __bfloat162float(h1);
        size_t off = ((size_t)(b * 63 + m) * K + t) >> 1;
        EH[off] = __halves2bfloat162(h0, h1);
        EL[off] = __halves2bfloat162(__float2bfloat16(l0), __float2bfloat16(l1));
    }
}

// ======================= fp32 MLP layer-1 GEMM (tiny) =======================
__global__ __launch_bounds__(256) void mlp_gemm0(
    const float* __restrict__ A, const float* __restrict__ W,
    const float* __restrict__ bias, float* __restrict__ P, int K, int N) {
    __shared__ float As[16][64];
    __shared__ float Bs[16][64];
    int tid = threadIdx.x;
    int bm = blockIdx.x * 64, bn = blockIdx.y * 64;
    int lr = tid >> 2, lk = (tid & 3) * 4;
    int tx = tid & 15, ty = tid >> 4;
    float acc[4][4];
#pragma unroll
    for (int r = 0; r < 4; r++)
#pragma unroll
        for (int c = 0; c < 4; c++) acc[r][c] = 0.f;
    for (int k0 = 0; k0 < K; k0 += 16) {
        float4 a = *(const float4*)(A + (size_t)(bm + lr) * K + k0 + lk);
        float4 w4 = *(const float4*)(W + (size_t)(bn + lr) * K + k0 + lk);
        As[lk + 0][lr] = a.x; As[lk + 1][lr] = a.y;
        As[lk + 2][lr] = a.z; As[lk + 3][lr] = a.w;
        Bs[lk + 0][lr] = w4.x; Bs[lk + 1][lr] = w4.y;
        Bs[lk + 2][lr] = w4.z; Bs[lk + 3][lr] = w4.w;
        __syncthreads();
#pragma unroll
        for (int kk = 0; kk < 16; kk++) {
            float4 av = *(const float4*)&As[kk][ty * 4];
            float4 bv = *(const float4*)&Bs[kk][tx * 4];
            acc[0][0] += av.x * bv.x; acc[0][1] += av.x * bv.y;
            acc[0][2] += av.x * bv.z; acc[0][3] += av.x * bv.w;
            acc[1][0] += av.y * bv.x; acc[1][1] += av.y * bv.y;
            acc[1][2] += av.y * bv.z; acc[1][3] += av.y * bv.w;
            acc[2][0] += av.z * bv.x; acc[2][1] += av.z * bv.y;
            acc[2][2] += av.z * bv.z; acc[2][3] += av.z * bv.w;
            acc[3][0] += av.w * bv.x; acc[3][1] += av.w * bv.y;
            acc[3][2] += av.w * bv.z; acc[3][3] += av.w * bv.w;
        }
        __syncthreads();
    }
#pragma unroll
    for (int r = 0; r < 4; r++) {
        int i = bm + ty * 4 + r;
#pragma unroll
        for (int c = 0; c < 4; c++) {
            int j = bn + tx * 4 + c;
            P[(size_t)i * N + j] = acc[r][c] + bias[j];
        }
    }
}

// ---------------- BN stats: per-column mean/var -> scale/shift ----------------
__global__ void bnstats_kernel(const float* __restrict__ P, int N,
                               const float* __restrict__ g,
                               const float* __restrict__ be,
                               float* __restrict__ sc, float* __restrict__ sh) {
    __shared__ float ss[8][32], sq[8][32];
    int c = blockIdx.x * 32 + threadIdx.x;
    float s = 0.f, q = 0.f;
    for (int r = threadIdx.y; r < BB; r += 8) {
        float v = P[(size_t)r * N + c];
        s += v;
        q += v * v;
    }
    ss[threadIdx.y][threadIdx.x] = s;
    sq[threadIdx.y][threadIdx.x] = q;
    __syncthreads();
    if (threadIdx.y == 0) {
#pragma unroll
        for (int y = 1; y < 8; y++) {
            s += ss[y][threadIdx.x];
            q += sq[y][threadIdx.x];
        }
        float m = s * (1.f / BB);
        float var = q * (1.f / BB) - m * m;
        float a = g[c] * rsqrtf(var + 1e-5f);
        sc[c] = a;
        sh[c] = be[c] - a * m;
    }
}

// ---------------- final fused tree-norm: stats + apply + lrelu, smem-staged ----
// one block per sample; n = 512*64 floats = 128KB smem
__global__ __launch_bounds__(256) void tnfinal_kernel(float* __restrict__ X, int n) {
    extern __shared__ float s[];
    __shared__ float rs[256], rq[256];
    int b = blockIdx.x, tid = threadIdx.x;
    float4* src = (float4*)(X + (size_t)b * n);
    float4* sv = (float4*)s;
    float ss = 0.f, qq = 0.f;
    int n4 = n >> 2;
    for (int i = tid; i < n4; i += 256) {
        float4 v = src[i];
        sv[i] = v;
        ss += v.x + v.y + v.z + v.w;
        qq += v.x * v.x + v.y * v.y + v.z * v.z + v.w * v.w;
    }
    rs[tid] = ss;
    rq[tid] = qq;
    __syncthreads();
    for (int st = 128; st > 0; st >>= 1) {
        if (tid < st) {
            rs[tid] += rs[tid + st];
            rq[tid] += rq[tid + st];
        }
        __syncthreads();
    }
    float m = rs[0] / (float)n;
    float var = (rq[0] - (float)n * m * m) / (float)(n - 1);
    var = fmaxf(var, 0.f);
    float r = 1.f / (sqrtf(var) + 1e-5f);
    for (int i = tid; i < n4; i += 256) {
        float4 v = sv[i];
        v.x = (v.x - m) * r; v.x = v.x > 0.f ? v.x : 0.01f * v.x;
        v.y = (v.y - m) * r; v.y = v.y > 0.f ? v.y : 0.01f * v.y;
        v.z = (v.z - m) * r; v.z = v.z > 0.f ? v.z : 0.01f * v.z;
        v.w = (v.w - m) * r; v.w = v.w > 0.f ? v.w : 0.01f * v.w;
        src[i] = v;
    }
}

// ======================= host launch =======================
extern "C" void kernel_launch(void* const* d_in, const int* in_sizes, int n_in,
                              void* d_out, int out_size) {
    const float* trees = (const float*)d_in[0];
    const int* indexes = (const int*)d_in[1];
    const float* w1 = (const float*)d_in[2];
    const float* b1 = (const float*)d_in[3];
    const float* g1 = (const float*)d_in[4];
    const float* be1 = (const float*)d_in[5];
    const float* w2 = (const float*)d_in[6];
    const float* b2 = (const float*)d_in[7];
    const float* g2 = (const float*)d_in[8];
    const float* be2 = (const float*)d_in[9];
    const float* w3 = (const float*)d_in[10];
    const float* b3 = (const float*)d_in[11];
    const float* g3 = (const float*)d_in[12];
    const float* be3 = (const float*)d_in[13];
    const float* w4 = (const float*)d_in[14];
    const float* b4 = (const float*)d_in[15];
    const float* g4 = (const float*)d_in[16];
    const float* be4 = (const float*)d_in[17];
    const float* cw1 = (const float*)d_in[18];
    const float* cb1 = (const float*)d_in[19];
    const float* cw2 = (const float*)d_in[20];
    const float* cb2 = (const float*)d_in[21];
    const float* cw3 = (const float*)d_in[22];
    const float* cb3 = (const float*)d_in[23];
    float* out = (float*)d_out;

    float *p_h1, *p_h2, *p_h3, *p_h4, *p_t1, *p_t2, *p_sc, *p_sh;
    __nv_bfloat16 *p_Eh, *p_El, *p_Wh, *p_Wl;
    cudaGetSymbolAddress((void**)&p_h1, g_h1);
    cudaGetSymbolAddress((void**)&p_h2, g_h2);
    cudaGetSymbolAddress((void**)&p_h3, g_h3);
    cudaGetSymbolAddress((void**)&p_h4, g_h4);
    cudaGetSymbolAddress((void**)&p_t1, g_t1);
    cudaGetSymbolAddress((void**)&p_t2, g_t2);
    cudaGetSymbolAddress((void**)&p_sc, g_sc);
    cudaGetSymbolAddress((void**)&p_sh, g_sh);
    cudaGetSymbolAddress((void**)&p_Eh, g_Eh);
    cudaGetSymbolAddress((void**)&p_El, g_El);
    cudaGetSymbolAddress((void**)&p_Wh, g_Wh);
    cudaGetSymbolAddress((void**)&p_Wl, g_Wl);

    cudaFuncSetAttribute(mma_gemm<0>, cudaFuncAttributeMaxDynamicSharedMemorySize, GSM_TOTAL);
    cudaFuncSetAttribute(mma_gemm<1>, cudaFuncAttributeMaxDynamicSharedMemorySize, GSM_TOTAL);
    cudaFuncSetAttribute(gather_kernel<256, 1>, cudaFuncAttributeMaxDynamicSharedMemorySize, 256 * 64 * 4);
    cudaFuncSetAttribute(tnfinal_kernel, cudaFuncAttributeMaxDynamicSharedMemorySize, 512 * 64 * 4);

    dim3 bst(32, 8);

    // ---- MLP layer 1 (fp32, tiny) ----
    mlp_gemm0<<<dim3(32, 1), 256>>>(trees, w1, b1, p_h1, 64, 64);
    bnstats_kernel<<<2, bst>>>(p_h1, 64, g1, be1, p_sc, p_sh);

    // ---- MLP layer 2: 2048x256, K=64 ----
    actsplit_kernel<<<(BB * 64 + 255) / 256, 256>>>(p_h1, p_sc, p_sh, p_Eh, p_El, 63, BB * 64);
    wsplit_kernel<<<(256 * 64 + 255) / 256, 256>>>(w2, p_Wh, p_Wl, 256 * 64);
    mma_gemm<0><<<dim3(2, 8), 256, GSM_TOTAL>>>(p_Eh, p_El, p_Wh, p_Wl, b2, p_h2, 64, 256);
    bnstats_kernel<<<8, bst>>>(p_h2, 256, g2, be2, p_sc, p_sh);

    // ---- MLP layer 3: 2048x1024, K=256 ----
    actsplit_kernel<<<(BB * 256 + 255) / 256, 256>>>(p_h2, p_sc, p_sh, p_Eh, p_El, 255, BB * 256);
    wsplit_kernel<<<(1024 * 256 + 255) / 256, 256>>>(w3, p_Wh, p_Wl, 1024 * 256);
    mma_gemm<0><<<dim3(8, 8), 256, GSM_TOTAL>>>(p_Eh, p_El, p_Wh, p_Wl, b3, p_h3, 256, 1024);
    bnstats_kernel<<<32, bst>>>(p_h3, 1024, g3, be3, p_sc, p_sh);

    // ---- MLP layer 4: 2048x4096, K=1024 ----
    actsplit_kernel<<<(BB * 1024 + 255) / 256, 256>>>(p_h3, p_sc, p_sh, p_Eh, p_El, 1023, BB * 1024);
    wsplit_kernel<<<(4096 * 1024 + 255) / 256, 256>>>(w4, p_Wh, p_Wl, 4096 * 1024);
    mma_gemm<0><<<dim3(32, 8), 256, GSM_TOTAL>>>(p_Eh, p_El, p_Wh, p_Wl, b4, p_h4, 1024, 4096);
    bnstats_kernel<<<128, bst>>>(p_h4, 4096, g4, be4, p_sc, p_sh);

    // ---- tree conv 1: M=129024, N=128, K=192 ----
    gather_kernel<64, 0><<<BB, 256, 64 * 64 * 4>>>(p_h4, indexes, p_sc, p_sh, p_Eh, p_El);
    wsplit_kernel<<<(128 * 192 + 255) / 256, 256>>>(cw1, p_Wh, p_Wl, 128 * 192);
    mma_gemm<1><<<dim3(1, 504), 256, GSM_TOTAL>>>(p_Eh, p_El, p_Wh, p_Wl, cb1, p_t1, 192, 128);

    // ---- tree conv 2: N=256, K=384 (tree-norm of t1 fused into gather) ----
    gather_kernel<128, 1><<<BB, 256, 128 * 64 * 4>>>(p_t1, indexes, nullptr, nullptr, p_Eh, p_El);
    wsplit_kernel<<<(256 * 384 + 255) / 256, 256>>>(cw2, p_Wh, p_Wl, 256 * 384);
    mma_gemm<1><<<dim3(2, 504), 256, GSM_TOTAL>>>(p_Eh, p_El, p_Wh, p_Wl, cb2, p_t2, 384, 256);

    // ---- tree conv 3: N=512, K=768 -> d_out (tree-norm of t2 fused into gather) ----
    gather_kernel<256, 1><<<BB, 256, 256 * 64 * 4>>>(p_t2, indexes, nullptr, nullptr, p_Eh, p_El);
    wsplit_kernel<<<(512 * 768 + 255) / 256, 256>>>(cw3, p_Wh, p_Wl, 512 * 768);
    mma_gemm<1><<<dim3(4, 504), 256, GSM_TOTAL>>>(p_Eh, p_El, p_Wh, p_Wl, cb3, out, 768, 512);

    // ---- final tree-norm + lrelu, fused single pass ----
    tnfinal_kernel<<<BB, 256, 512 * 64 * 4>>>(out, 512 * 64);
}